// round 15
// baseline (speedup 1.0000x reference)
#include <cuda_runtime.h>
#include <cuda_bf16.h>
#include <math.h>
#include <stdint.h>

#define NN  100000
#define EE  1600000
#define IND 512
#define HGD 64
#define OUTD 20

#define SCAN_BLK 1024
#define NBLK ((NN + SCAN_BLK - 1) / SCAN_BLK)   // 98

typedef unsigned long long ull;

// ---------------- scratch (static device globals; no allocs) ----------------
__device__ __align__(8) float2 g_dc[NN];  // (deg, cnt) accumulated together
__device__ float g_deg[NN];               // dinv after scan_add
__device__ int   g_rowptr[NN + 1];
__device__ int   g_cursor[NN];
__device__ int   g_bsum[NBLK];
__device__ __align__(8) int2 g_ce[EE];    // CSR: (src, norm-bits) packed
__device__ __align__(16) float g_xw[(size_t)NN * HGD];
__device__ __align__(16) float g_h[(size_t)NN * HGD];
// conv weights split-bf16 images, [n][k] layout
__device__ __align__(16) __nv_bfloat16 g_wbh[64 * 512];   // gc0_w
__device__ __align__(16) __nv_bfloat16 g_wbl[64 * 512];
__device__ __align__(16) __nv_bfloat16 g_w1h[64 * 64];    // gc1_w
__device__ __align__(16) __nv_bfloat16 g_w1l[64 * 64];
// dense weights split-bf16 images: [L][n][k], L=0..2 (64x64), W3 padded 32x64
__device__ __align__(16) __nv_bfloat16 g_wdh[3 * 64 * 64];
__device__ __align__(16) __nv_bfloat16 g_wdl[3 * 64 * 64];
__device__ __align__(16) __nv_bfloat16 g_w3h[32 * 64];
__device__ __align__(16) __nv_bfloat16 g_w3l[32 * 64];

__device__ __forceinline__ float selu_f(float x) {
    const float a = 1.6732632423543772f, s = 1.0507009873554805f;
    return s * (x > 0.f ? x : a * expm1f(x));
}

// warp-level bf16 MMA (sm_80+ PTX)
__device__ __forceinline__ void mma_bf16(float* c, const uint32_t* a, uint32_t b0, uint32_t b1) {
    asm volatile(
        "mma.sync.aligned.m16n8k16.row.col.f32.bf16.bf16.f32 "
        "{%0,%1,%2,%3}, {%4,%5,%6,%7}, {%8,%9}, {%0,%1,%2,%3};"
        : "+f"(c[0]), "+f"(c[1]), "+f"(c[2]), "+f"(c[3])
        : "r"(a[0]), "r"(a[1]), "r"(a[2]), "r"(a[3]), "r"(b0), "r"(b1));
}

__device__ __forceinline__ void ldsm4(uint32_t* r, uint32_t addr) {
    asm volatile("ldmatrix.sync.aligned.m8n8.x4.shared.b16 {%0,%1,%2,%3}, [%4];"
                 : "=r"(r[0]), "=r"(r[1]), "=r"(r[2]), "=r"(r[3]) : "r"(addr));
}

__device__ __forceinline__ uint32_t smem_u32(const void* p) {
    uint32_t a;
    asm("{ .reg .u64 t; cvta.to.shared.u64 t, %1; cvt.u32.u64 %0, t; }" : "=r"(a) : "l"(p));
    return a;
}

// split f32 pair -> packed bf16x2 (hi, lo)
__device__ __forceinline__ void split2(float x, float y, uint32_t& hi, uint32_t& lo) {
    __nv_bfloat16 hx = __float2bfloat16(x), hy = __float2bfloat16(y);
    __nv_bfloat162 h; h.x = hx; h.y = hy;
    __nv_bfloat162 l; l.x = __float2bfloat16(x - __bfloat162float(hx));
                      l.y = __float2bfloat16(y - __bfloat162float(hy));
    hi = *(uint32_t*)&h;
    lo = *(uint32_t*)&l;
}

// ---------------- degree + count ----------------
__global__ void k_deg_init() {
    int i = blockIdx.x * blockDim.x + threadIdx.x;
    if (i < NN) g_dc[i] = make_float2(1.0f, 0.0f);   // self-loop weight 1
}

__global__ void k_deg_acc(const int* __restrict__ ei, const float* __restrict__ w) {
    int e = blockIdx.x * blockDim.x + threadIdx.x;
    if (e < EE) {
        int c = ei[EE + e];
        asm volatile("red.global.add.v2.f32 [%0], {%1, %2};"
                     :: "l"(&g_dc[c]), "f"(w[e]), "f"(1.0f) : "memory");
    }
}

// ---------------- exclusive scan over cnt -> g_rowptr ----------------
__global__ void k_scan1() {
    __shared__ int sh[SCAN_BLK];
    int i = blockIdx.x * SCAN_BLK + threadIdx.x;
    int v = (i < NN) ? (int)g_dc[i].y : 0;
    sh[threadIdx.x] = v;
    __syncthreads();
    for (int off = 1; off < SCAN_BLK; off <<= 1) {
        int t = (threadIdx.x >= off) ? sh[threadIdx.x - off] : 0;
        __syncthreads();
        sh[threadIdx.x] += t;
        __syncthreads();
    }
    if (i < NN) g_rowptr[i] = sh[threadIdx.x] - v;
    if (threadIdx.x == SCAN_BLK - 1) g_bsum[blockIdx.x] = sh[threadIdx.x];
}

// scan_add with inline top-level prefix; also computes dinv
__global__ void k_scan_add() {
    __shared__ int sred[128];
    int tidx = threadIdx.x;
    if (tidx < 128)
        sred[tidx] = (tidx < NBLK && tidx < blockIdx.x) ? g_bsum[tidx] : 0;
    __syncthreads();
    if (tidx < 64) sred[tidx] += sred[tidx + 64];
    __syncthreads();
    if (tidx < 32) {
        int s = sred[tidx] + sred[tidx + 32];
        s += __shfl_down_sync(0xffffffffu, s, 16);
        s += __shfl_down_sync(0xffffffffu, s, 8);
        s += __shfl_down_sync(0xffffffffu, s, 4);
        s += __shfl_down_sync(0xffffffffu, s, 2);
        s += __shfl_down_sync(0xffffffffu, s, 1);
        if (tidx == 0) sred[0] = s;
    }
    __syncthreads();
    int prefix = sred[0];

    int i = blockIdx.x * SCAN_BLK + tidx;
    if (i < NN) {
        int r = g_rowptr[i] + prefix;
        g_rowptr[i] = r;
        g_cursor[i] = r;
        float d = g_dc[i].x;
        g_deg[i] = d > 0.f ? rsqrtf(fmaxf(d, 1e-30f)) : 0.f;
    }
    if (i == 0) g_rowptr[NN] = EE;
}

// ---------------- CSR fill (packed int2) ----------------
__global__ void k_fill(const int* __restrict__ ei, const float* __restrict__ w) {
    int e = blockIdx.x * blockDim.x + threadIdx.x;
    if (e < EE) {
        int r = ei[e];
        int c = ei[EE + e];
        int pos = atomicAdd(&g_cursor[c], 1);
        float nm = g_deg[r] * w[e] * g_deg[c];
        g_ce[pos] = make_int2(r, __float_as_int(nm));
    }
}

// ---------------- conv weights -> split-bf16 images, [n][k] -----------------
__global__ void k_wb(const float* __restrict__ W0, const float* __restrict__ W1) {
    int i = blockIdx.x * blockDim.x + threadIdx.x;
    if (i < 512 * 64) {
        int k = i >> 6, n = i & 63;
        float w = W0[i];
        __nv_bfloat16 hi = __float2bfloat16(w);
        __nv_bfloat16 lo = __float2bfloat16(w - __bfloat162float(hi));
        g_wbh[n * 512 + k] = hi;
        g_wbl[n * 512 + k] = lo;
    } else if (i < 512 * 64 + 64 * 64) {
        int r = i - 512 * 64;
        int k = r >> 6, n = r & 63;
        float w = W1[r];
        __nv_bfloat16 hi = __float2bfloat16(w);
        __nv_bfloat16 lo = __float2bfloat16(w - __bfloat162float(hi));
        g_w1h[n * 64 + k] = hi;
        g_w1l[n * 64 + k] = lo;
    }
}

// ---------------- dense weights -> split-bf16 images ------------------------
__global__ void k_wd(const float* __restrict__ w0, const float* __restrict__ w1,
                     const float* __restrict__ w2, const float* __restrict__ w3) {
    int i = blockIdx.x * blockDim.x + threadIdx.x;
    if (i < 3 * 4096) {
        int L = i >> 12, r = i & 4095;
        int k = r >> 6, n = r & 63;
        const float* W = (L == 0) ? w0 : ((L == 1) ? w1 : w2);
        float v = W[k * 64 + n];
        __nv_bfloat16 hi = __float2bfloat16(v);
        __nv_bfloat16 lo = __float2bfloat16(v - __bfloat162float(hi));
        g_wdh[L * 4096 + n * 64 + k] = hi;
        g_wdl[L * 4096 + n * 64 + k] = lo;
    } else if (i < 3 * 4096 + 2048) {
        int r = i - 12288;
        int n = r >> 6, k = r & 63;
        float v = (n < 20) ? w3[k * 20 + n] : 0.f;
        __nv_bfloat16 hi = __float2bfloat16(v);
        __nv_bfloat16 lo = __float2bfloat16(v - __bfloat162float(hi));
        g_w3h[n * 64 + k] = hi;
        g_w3l[n * 64 + k] = lo;
    }
}

// ---------------- shared gather phase: CSR gather -> split-bf16 smem A ------
// 256 threads cover 128 nodes in 8 passes (16 lanes/node, 1 float4 each).
#define ASTR 72
__device__ __forceinline__ void gather_to_smem(
    const float* __restrict__ src, const float* __restrict__ bias,
    __nv_bfloat16* Ah, __nv_bfloat16* Al, int row0, int tid, int M) {
#pragma unroll 1
    for (int pass = 0; pass < 8; pass++) {
        int r = pass * 16 + (tid >> 4);
        int n = row0 + r;
        int q = (tid & 15) << 2;
        float4 o = make_float4(0.f, 0.f, 0.f, 0.f);
        if (n < M) {
            float d = g_deg[n];
            float dd = d * d;
            float4 v = *(const float4*)&src[(size_t)n * 64 + q];
            float4 acc = make_float4(v.x * dd, v.y * dd, v.z * dd, v.w * dd);
            int s = g_rowptr[n], e2 = g_rowptr[n + 1];
            int i = s;
            for (; i + 1 < e2; i += 2) {
                int2 p0 = g_ce[i];
                int2 p1 = g_ce[i + 1];
                float n0 = __int_as_float(p0.y), n1 = __int_as_float(p1.y);
                float4 u0 = *(const float4*)&src[(size_t)p0.x * 64 + q];
                float4 u1 = *(const float4*)&src[(size_t)p1.x * 64 + q];
                acc.x += n0 * u0.x + n1 * u1.x;
                acc.y += n0 * u0.y + n1 * u1.y;
                acc.z += n0 * u0.z + n1 * u1.z;
                acc.w += n0 * u0.w + n1 * u1.w;
            }
            if (i < e2) {
                int2 p0 = g_ce[i];
                float n0 = __int_as_float(p0.y);
                float4 u0 = *(const float4*)&src[(size_t)p0.x * 64 + q];
                acc.x += n0 * u0.x;
                acc.y += n0 * u0.y;
                acc.z += n0 * u0.z;
                acc.w += n0 * u0.w;
            }
            float4 b4 = *(const float4*)&bias[q];
            o.x = selu_f(acc.x + b4.x);
            o.y = selu_f(acc.y + b4.y);
            o.z = selu_f(acc.z + b4.z);
            o.w = selu_f(acc.w + b4.w);
        }
        uint32_t h0, l0, h1, l1;
        split2(o.x, o.y, h0, l0);
        split2(o.z, o.w, h1, l1);
        int so = r * ASTR + q;
        *(uint32_t*)(Ah + so)     = h0;
        *(uint32_t*)(Ah + so + 2) = h1;
        *(uint32_t*)(Al + so)     = l0;
        *(uint32_t*)(Al + so + 2) = l1;
    }
}

// ---------------- conv0 GEMM on mma.sync (split-bf16, ldmatrix), K=512 -----
#define SM_AHI_O 0
#define SM_ALO_O 18432
#define SM_BHI_O 36864
#define SM_BLO_O 46080
#define SM_MMA_TOT 55296
__global__ void k_conv_mma(const float* __restrict__ A, float* __restrict__ C, int M, int K,
                           const __nv_bfloat16* __restrict__ WH,
                           const __nv_bfloat16* __restrict__ WL) {
    extern __shared__ __align__(16) char smem[];
    __nv_bfloat16* Ah = (__nv_bfloat16*)(smem + SM_AHI_O);
    __nv_bfloat16* Al = (__nv_bfloat16*)(smem + SM_ALO_O);
    __nv_bfloat16* Bh = (__nv_bfloat16*)(smem + SM_BHI_O);
    __nv_bfloat16* Bl = (__nv_bfloat16*)(smem + SM_BLO_O);

    int tid = threadIdx.x;
    int w = tid >> 5, lane = tid & 31;
    int gr = lane >> 2, t = lane & 3;
    int row0 = blockIdx.x * 128;
    uint32_t sb = smem_u32(smem);

    uint32_t a_off = (uint32_t)((w * 16 + (lane & 7) + ((lane >> 3) & 1) * 8) * 144
                                + ((lane >> 4) & 1) * 16);
    uint32_t b_off_base = (uint32_t)((((lane >> 4) & 1) * 8 + (lane & 7)) * 144
                                     + ((lane >> 3) & 1) * 16);

    float acc[8][4];
#pragma unroll
    for (int i = 0; i < 8; i++)
#pragma unroll
        for (int j = 0; j < 4; j++) acc[i][j] = 0.f;

    int chunks = K >> 6;
    for (int c = 0; c < chunks; c++) {
#pragma unroll
        for (int it = 0; it < 8; it++) {
            int idx = tid + it * 256;
            int r = idx >> 4;
            int kq = (idx & 15) * 4;
            int row = row0 + r;
            float4 v = (row < M) ? *(const float4*)&A[(size_t)row * K + c * 64 + kq]
                                 : make_float4(0.f, 0.f, 0.f, 0.f);
            uint32_t h0, l0, h1, l1;
            split2(v.x, v.y, h0, l0);
            split2(v.z, v.w, h1, l1);
            int so = r * ASTR + kq;
            *(uint32_t*)(Ah + so)     = h0;
            *(uint32_t*)(Ah + so + 2) = h1;
            *(uint32_t*)(Al + so)     = l0;
            *(uint32_t*)(Al + so + 2) = l1;
        }
#pragma unroll
        for (int it = 0; it < 2; it++) {
            int i = tid + it * 256;
            int n = i >> 3, j = i & 7;
            uint4 vh = *((const uint4*)(WH + (size_t)n * K + c * 64) + j);
            uint4 vl = *((const uint4*)(WL + (size_t)n * K + c * 64) + j);
            *((uint4*)((char*)Bh + n * 144) + j) = vh;
            *((uint4*)((char*)Bl + n * 144) + j) = vl;
        }
        __syncthreads();

#pragma unroll
        for (int ks = 0; ks < 4; ks++) {
            uint32_t kadd = (uint32_t)(ks * 32);
            uint32_t ah[4], al[4];
            ldsm4(ah, sb + SM_AHI_O + a_off + kadd);
            ldsm4(al, sb + SM_ALO_O + a_off + kadd);
#pragma unroll
            for (int p = 0; p < 4; p++) {
                uint32_t boff = b_off_base + (uint32_t)(p * 16 * 144) + kadd;
                uint32_t bh[4], bl[4];
                ldsm4(bh, sb + SM_BHI_O + boff);
                ldsm4(bl, sb + SM_BLO_O + boff);
                mma_bf16(acc[2 * p],     ah, bh[0], bh[1]);
                mma_bf16(acc[2 * p],     al, bh[0], bh[1]);
                mma_bf16(acc[2 * p],     ah, bl[0], bl[1]);
                mma_bf16(acc[2 * p + 1], ah, bh[2], bh[3]);
                mma_bf16(acc[2 * p + 1], al, bh[2], bh[3]);
                mma_bf16(acc[2 * p + 1], ah, bl[2], bl[3]);
            }
        }
        __syncthreads();
    }

    int r1 = row0 + w * 16 + gr;
    int r2 = r1 + 8;
#pragma unroll
    for (int nt = 0; nt < 8; nt++) {
        int col = nt * 8 + t * 2;
        if (r1 < M) *(float2*)&C[(size_t)r1 * 64 + col] = make_float2(acc[nt][0], acc[nt][1]);
        if (r2 < M) *(float2*)&C[(size_t)r2 * 64 + col] = make_float2(acc[nt][2], acc[nt][3]);
    }
}

// ---------------- fused gather0 + conv1 GEMM (K=64) ------------------------
// gathers from g_xw (conv0 out) with gc0 bias -> h1 in smem -> mma W1 -> g_h
__global__ void k_gconv(const float* __restrict__ bias,
                        const __nv_bfloat16* __restrict__ WH,
                        const __nv_bfloat16* __restrict__ WL,
                        const float* __restrict__ src, float* __restrict__ C, int M) {
    extern __shared__ __align__(16) char smem[];
    __nv_bfloat16* Ah = (__nv_bfloat16*)(smem + SM_AHI_O);
    __nv_bfloat16* Al = (__nv_bfloat16*)(smem + SM_ALO_O);
    __nv_bfloat16* Bh = (__nv_bfloat16*)(smem + SM_BHI_O);
    __nv_bfloat16* Bl = (__nv_bfloat16*)(smem + SM_BLO_O);

    int tid = threadIdx.x;
    int w = tid >> 5, lane = tid & 31;
    int gr = lane >> 2, t = lane & 3;
    int row0 = blockIdx.x * 128;
    uint32_t sb = smem_u32(smem);

    // gather phase -> A buffers; stage B (K=64) meanwhile pattern-free
    gather_to_smem(src, bias, Ah, Al, row0, tid, M);
#pragma unroll
    for (int it = 0; it < 2; it++) {
        int i = tid + it * 256;
        int n = i >> 3, j = i & 7;
        uint4 vh = *((const uint4*)(WH + (size_t)n * 64) + j);
        uint4 vl = *((const uint4*)(WL + (size_t)n * 64) + j);
        *((uint4*)((char*)Bh + n * 144) + j) = vh;
        *((uint4*)((char*)Bl + n * 144) + j) = vl;
    }
    __syncthreads();

    uint32_t a_off = (uint32_t)((w * 16 + (lane & 7) + ((lane >> 3) & 1) * 8) * 144
                                + ((lane >> 4) & 1) * 16);
    uint32_t b_off_base = (uint32_t)((((lane >> 4) & 1) * 8 + (lane & 7)) * 144
                                     + ((lane >> 3) & 1) * 16);

    float acc[8][4];
#pragma unroll
    for (int i = 0; i < 8; i++)
#pragma unroll
        for (int j = 0; j < 4; j++) acc[i][j] = 0.f;

#pragma unroll
    for (int ks = 0; ks < 4; ks++) {
        uint32_t kadd = (uint32_t)(ks * 32);
        uint32_t ah[4], al[4];
        ldsm4(ah, sb + SM_AHI_O + a_off + kadd);
        ldsm4(al, sb + SM_ALO_O + a_off + kadd);
#pragma unroll
        for (int p = 0; p < 4; p++) {
            uint32_t boff = b_off_base + (uint32_t)(p * 16 * 144) + kadd;
            uint32_t bh[4], bl[4];
            ldsm4(bh, sb + SM_BHI_O + boff);
            ldsm4(bl, sb + SM_BLO_O + boff);
            mma_bf16(acc[2 * p],     ah, bh[0], bh[1]);
            mma_bf16(acc[2 * p],     al, bh[0], bh[1]);
            mma_bf16(acc[2 * p],     ah, bl[0], bl[1]);
            mma_bf16(acc[2 * p + 1], ah, bh[2], bh[3]);
            mma_bf16(acc[2 * p + 1], al, bh[2], bh[3]);
            mma_bf16(acc[2 * p + 1], ah, bl[2], bl[3]);
        }
    }

    int r1 = row0 + w * 16 + gr;
    int r2 = r1 + 8;
#pragma unroll
    for (int nt = 0; nt < 8; nt++) {
        int col = nt * 8 + t * 2;
        if (r1 < M) *(float2*)&C[(size_t)r1 * 64 + col] = make_float2(acc[nt][0], acc[nt][1]);
        if (r2 < M) *(float2*)&C[(size_t)r2 * 64 + col] = make_float2(acc[nt][2], acc[nt][3]);
    }
}

// ---------------- fused gather1 + dense MLP + softmax ----------------------
#define DM_AH 0
#define DM_AL 18432
#define DM_BH 36864
#define DM_BL 46080
#define DM_BS 55296
#define DM_TOT 55552
__global__ void k_gdense(const float* __restrict__ gbias,
                         const float* __restrict__ b0, const float* __restrict__ b1,
                         const float* __restrict__ b2, const float* __restrict__ b3,
                         const float* __restrict__ src, float* __restrict__ out, int M) {
    extern __shared__ __align__(16) char smem[];
    __nv_bfloat16* Ah = (__nv_bfloat16*)(smem + DM_AH);
    __nv_bfloat16* Al = (__nv_bfloat16*)(smem + DM_AL);
    float* bs = (float*)(smem + DM_BS);

    int tid = threadIdx.x;
    int w = tid >> 5, lane = tid & 31;
    int gr = lane >> 2, t = lane & 3;
    int row0 = blockIdx.x * 128;
    uint32_t sb = smem_u32(smem);

    uint32_t a_off = (uint32_t)((w * 16 + (lane & 7) + ((lane >> 3) & 1) * 8) * 144
                                + ((lane >> 4) & 1) * 16);
    uint32_t b_off_base = (uint32_t)((((lane >> 4) & 1) * 8 + (lane & 7)) * 144
                                     + ((lane >> 3) & 1) * 16);

    // gather phase -> initial A
    gather_to_smem(src, gbias, Ah, Al, row0, tid, M);

    const float* Bp[3] = {b0, b1, b2};

    for (int L = 0; L < 3; L++) {
#pragma unroll
        for (int it = 0; it < 2; it++) {
            int i = tid + it * 256;
            int n = i >> 3, j = i & 7;
            uint4 vh = *((const uint4*)(g_wdh + L * 4096 + n * 64) + j);
            uint4 vl = *((const uint4*)(g_wdl + L * 4096 + n * 64) + j);
            *((uint4*)(smem + DM_BH + n * 144) + j) = vh;
            *((uint4*)(smem + DM_BL + n * 144) + j) = vl;
        }
        if (tid < 64) bs[tid] = Bp[L][tid];
        __syncthreads();

        float acc[8][4];
#pragma unroll
        for (int i = 0; i < 8; i++)
#pragma unroll
            for (int j = 0; j < 4; j++) acc[i][j] = 0.f;

#pragma unroll
        for (int ks = 0; ks < 4; ks++) {
            uint32_t kadd = (uint32_t)(ks * 32);
            uint32_t ah[4], al[4];
            ldsm4(ah, sb + DM_AH + a_off + kadd);
            ldsm4(al, sb + DM_AL + a_off + kadd);
#pragma unroll
            for (int p = 0; p < 4; p++) {
                uint32_t boff = b_off_base + (uint32_t)(p * 16 * 144) + kadd;
                uint32_t bh[4], bl[4];
                ldsm4(bh, sb + DM_BH + boff);
                ldsm4(bl, sb + DM_BL + boff);
                mma_bf16(acc[2 * p],     ah, bh[0], bh[1]);
                mma_bf16(acc[2 * p],     al, bh[0], bh[1]);
                mma_bf16(acc[2 * p],     ah, bl[0], bl[1]);
                mma_bf16(acc[2 * p + 1], ah, bh[2], bh[3]);
                mma_bf16(acc[2 * p + 1], al, bh[2], bh[3]);
                mma_bf16(acc[2 * p + 1], ah, bl[2], bl[3]);
            }
        }

        uint32_t whi[8][2], wlo[8][2];
#pragma unroll
        for (int nt = 0; nt < 8; nt++) {
            float2 bb = *(const float2*)&bs[nt * 8 + 2 * t];
            float c0 = selu_f(acc[nt][0] + bb.x);
            float c1 = selu_f(acc[nt][1] + bb.y);
            float c2 = selu_f(acc[nt][2] + bb.x);
            float c3 = selu_f(acc[nt][3] + bb.y);
            split2(c0, c1, whi[nt][0], wlo[nt][0]);
            split2(c2, c3, whi[nt][1], wlo[nt][1]);
        }
        __syncthreads();
        int ra = (w * 16 + gr) * ASTR;
        int rb = (w * 16 + gr + 8) * ASTR;
#pragma unroll
        for (int nt = 0; nt < 8; nt++) {
            int co = nt * 8 + 2 * t;
            *(uint32_t*)(Ah + ra + co) = whi[nt][0];
            *(uint32_t*)(Al + ra + co) = wlo[nt][0];
            *(uint32_t*)(Ah + rb + co) = whi[nt][1];
            *(uint32_t*)(Al + rb + co) = wlo[nt][1];
        }
        __syncthreads();
    }

    // final layer: W3 padded to 32 rows
    {
        int i = tid;
        int n = i >> 3, j = i & 7;
        uint4 vh = *((const uint4*)(g_w3h + n * 64) + j);
        uint4 vl = *((const uint4*)(g_w3l + n * 64) + j);
        *((uint4*)(smem + DM_BH + n * 144) + j) = vh;
        *((uint4*)(smem + DM_BL + n * 144) + j) = vl;
    }
    if (tid < 24) bs[tid] = (tid < 20) ? b3[tid] : 0.f;
    __syncthreads();

    float accf[4][4];
#pragma unroll
    for (int i = 0; i < 4; i++)
#pragma unroll
        for (int j = 0; j < 4; j++) accf[i][j] = 0.f;

#pragma unroll
    for (int ks = 0; ks < 4; ks++) {
        uint32_t kadd = (uint32_t)(ks * 32);
        uint32_t ah[4], al[4];
        ldsm4(ah, sb + DM_AH + a_off + kadd);
        ldsm4(al, sb + DM_AL + a_off + kadd);
#pragma unroll
        for (int p = 0; p < 2; p++) {
            uint32_t boff = b_off_base + (uint32_t)(p * 16 * 144) + kadd;
            uint32_t bh[4], bl[4];
            ldsm4(bh, sb + DM_BH + boff);
            ldsm4(bl, sb + DM_BL + boff);
            mma_bf16(accf[2 * p],     ah, bh[0], bh[1]);
            mma_bf16(accf[2 * p],     al, bh[0], bh[1]);
            mma_bf16(accf[2 * p],     ah, bl[0], bl[1]);
            mma_bf16(accf[2 * p + 1], ah, bh[2], bh[3]);
            mma_bf16(accf[2 * p + 1], al, bh[2], bh[3]);
            mma_bf16(accf[2 * p + 1], ah, bl[2], bl[3]);
        }
    }

    float lg0[6], lg1[6];
#pragma unroll
    for (int nt = 0; nt < 3; nt++) {
        float2 bb = *(const float2*)&bs[nt * 8 + 2 * t];
        lg0[2 * nt]     = accf[nt][0] + bb.x;
        lg0[2 * nt + 1] = accf[nt][1] + bb.y;
        lg1[2 * nt]     = accf[nt][2] + bb.x;
        lg1[2 * nt + 1] = accf[nt][3] + bb.y;
    }
    bool v4 = (16 + 2 * t) < 20;
    if (!v4) { lg0[4] = lg0[5] = lg1[4] = lg1[5] = -1e30f; }

    float m0 = lg0[0], m1 = lg1[0];
#pragma unroll
    for (int i = 1; i < 6; i++) { m0 = fmaxf(m0, lg0[i]); m1 = fmaxf(m1, lg1[i]); }
    m0 = fmaxf(m0, __shfl_xor_sync(0xffffffffu, m0, 1));
    m0 = fmaxf(m0, __shfl_xor_sync(0xffffffffu, m0, 2));
    m1 = fmaxf(m1, __shfl_xor_sync(0xffffffffu, m1, 1));
    m1 = fmaxf(m1, __shfl_xor_sync(0xffffffffu, m1, 2));

    float e0[6], e1[6], s0 = 0.f, s1 = 0.f;
#pragma unroll
    for (int i = 0; i < 6; i++) {
        e0[i] = expf(lg0[i] - m0);
        e1[i] = expf(lg1[i] - m1);
        s0 += e0[i];
        s1 += e1[i];
    }
    s0 += __shfl_xor_sync(0xffffffffu, s0, 1);
    s0 += __shfl_xor_sync(0xffffffffu, s0, 2);
    s1 += __shfl_xor_sync(0xffffffffu, s1, 1);
    s1 += __shfl_xor_sync(0xffffffffu, s1, 2);
    float i0 = 1.f / s0, i1 = 1.f / s1;

    int r1 = row0 + w * 16 + gr;
    int r2 = r1 + 8;
#pragma unroll
    for (int nt = 0; nt < 3; nt++) {
        if (nt == 2 && !v4) continue;
        int col = nt * 8 + 2 * t;
        if (r1 < M) *(float2*)&out[(size_t)r1 * 20 + col] = make_float2(e0[2 * nt] * i0, e0[2 * nt + 1] * i0);
        if (r2 < M) *(float2*)&out[(size_t)r2 * 20 + col] = make_float2(e1[2 * nt] * i1, e1[2 * nt + 1] * i1);
    }
}

// ---------------- launch ----------------
extern "C" void kernel_launch(void* const* d_in, const int* in_sizes, int n_in,
                              void* d_out, int out_size) {
    const float* x    = (const float*)d_in[0];
    const int*   ei   = (const int*)d_in[1];      // int32 (JAX x64 disabled)
    const float* ea   = (const float*)d_in[2];
    const float* gc0w = (const float*)d_in[3];
    const float* gc0b = (const float*)d_in[4];
    const float* gc1w = (const float*)d_in[5];
    const float* gc1b = (const float*)d_in[6];
    const float* l0w  = (const float*)d_in[7];
    const float* l0b  = (const float*)d_in[8];
    const float* l1w  = (const float*)d_in[9];
    const float* l1b  = (const float*)d_in[10];
    const float* l2w  = (const float*)d_in[11];
    const float* l2b  = (const float*)d_in[12];
    const float* l3w  = (const float*)d_in[13];
    const float* l3b  = (const float*)d_in[14];
    float*       out  = (float*)d_out;

    float *xw, *h;
    cudaGetSymbolAddress((void**)&xw, g_xw);
    cudaGetSymbolAddress((void**)&h,  g_h);
    __nv_bfloat16 *wbh, *wbl, *w1h, *w1l;
    cudaGetSymbolAddress((void**)&wbh, g_wbh);
    cudaGetSymbolAddress((void**)&wbl, g_wbl);
    cudaGetSymbolAddress((void**)&w1h, g_w1h);
    cudaGetSymbolAddress((void**)&w1l, g_w1l);

    cudaFuncSetAttribute(k_conv_mma, cudaFuncAttributeMaxDynamicSharedMemorySize, SM_MMA_TOT);
    cudaFuncSetAttribute(k_gconv,    cudaFuncAttributeMaxDynamicSharedMemorySize, SM_MMA_TOT);
    cudaFuncSetAttribute(k_gdense,   cudaFuncAttributeMaxDynamicSharedMemorySize, DM_TOT);

    // second stream + fork/join events (host-side objects, created once)
    static cudaStream_t s2 = nullptr;
    static cudaEvent_t ev_fork = nullptr, ev_join = nullptr;
    if (s2 == nullptr) {
        cudaStreamCreateWithFlags(&s2, cudaStreamNonBlocking);
        cudaEventCreateWithFlags(&ev_fork, cudaEventDisableTiming);
        cudaEventCreateWithFlags(&ev_join, cudaEventDisableTiming);
    }

    const int T = 256;
    const int NBLK128 = (NN + 127) / 128;

    // fork: branch B (weight images + conv0 GEMM) on s2
    cudaEventRecord(ev_fork, 0);
    cudaStreamWaitEvent(s2, ev_fork, 0);
    k_wb<<<(512 * 64 + 64 * 64 + T - 1) / T, T, 0, s2>>>(gc0w, gc1w);
    k_wd<<<(14336 + T - 1) / T, T, 0, s2>>>(l0w, l1w, l2w, l3w);
    k_conv_mma<<<NBLK128, T, SM_MMA_TOT, s2>>>(x, xw, NN, IND, wbh, wbl);
    cudaEventRecord(ev_join, s2);

    // branch A (CSR build) on default stream
    k_deg_init<<<(NN + T - 1) / T, T>>>();
    k_deg_acc<<<(EE + T - 1) / T, T>>>(ei, ea);
    k_scan1<<<NBLK, SCAN_BLK>>>();
    k_scan_add<<<NBLK, SCAN_BLK>>>();
    k_fill<<<(EE + T - 1) / T, T>>>(ei, ea);

    // join, then fused gather0+conv1 (reads g_xw, writes g_h)
    cudaStreamWaitEvent(0, ev_join, 0);
    k_gconv<<<NBLK128, T, SM_MMA_TOT>>>(gc0b, w1h, w1l, xw, h, NN);

    // fused gather1 + dense stack + softmax (reads g_h, writes out)
    k_gdense<<<NBLK128, T, DM_TOT>>>(gc1b, l0b, l1b, l2b, l3b, h, out, NN);
}

// round 16
// speedup vs baseline: 1.0856x; 1.0856x over previous
#include <cuda_runtime.h>
#include <cuda_bf16.h>
#include <math.h>
#include <stdint.h>

#define NN  100000
#define EE  1600000
#define IND 512
#define HGD 64
#define OUTD 20

#define SCAN_BLK 1024
#define NBLK ((NN + SCAN_BLK - 1) / SCAN_BLK)   // 98

typedef unsigned long long ull;

// ---------------- scratch (static device globals; no allocs) ----------------
__device__ __align__(8) float2 g_dc[NN];  // (deg, cnt) accumulated together
__device__ float g_deg[NN];               // dinv after scan_add
__device__ int   g_rowptr[NN + 1];
__device__ int   g_cursor[NN];
__device__ int   g_bsum[NBLK];
__device__ __align__(8) int2 g_ce[EE];    // CSR: (src, norm-bits) packed
__device__ __align__(16) float g_xw[(size_t)NN * HGD];
__device__ __align__(16) float g_h[(size_t)NN * HGD];
// conv weights split-bf16 images, [n][k] layout
__device__ __align__(16) __nv_bfloat16 g_wbh[64 * 512];   // gc0_w
__device__ __align__(16) __nv_bfloat16 g_wbl[64 * 512];
__device__ __align__(16) __nv_bfloat16 g_w1h[64 * 64];    // gc1_w
__device__ __align__(16) __nv_bfloat16 g_w1l[64 * 64];
// dense weights split-bf16 images: [L][n][k], L=0..2 (64x64), W3 padded 32x64
__device__ __align__(16) __nv_bfloat16 g_wdh[3 * 64 * 64];
__device__ __align__(16) __nv_bfloat16 g_wdl[3 * 64 * 64];
__device__ __align__(16) __nv_bfloat16 g_w3h[32 * 64];
__device__ __align__(16) __nv_bfloat16 g_w3l[32 * 64];

__device__ __forceinline__ float selu_f(float x) {
    const float a = 1.6732632423543772f, s = 1.0507009873554805f;
    return s * (x > 0.f ? x : a * expm1f(x));
}

// warp-level bf16 MMA (sm_80+ PTX)
__device__ __forceinline__ void mma_bf16(float* c, const uint32_t* a, uint32_t b0, uint32_t b1) {
    asm volatile(
        "mma.sync.aligned.m16n8k16.row.col.f32.bf16.bf16.f32 "
        "{%0,%1,%2,%3}, {%4,%5,%6,%7}, {%8,%9}, {%0,%1,%2,%3};"
        : "+f"(c[0]), "+f"(c[1]), "+f"(c[2]), "+f"(c[3])
        : "r"(a[0]), "r"(a[1]), "r"(a[2]), "r"(a[3]), "r"(b0), "r"(b1));
}

__device__ __forceinline__ void ldsm4(uint32_t* r, uint32_t addr) {
    asm volatile("ldmatrix.sync.aligned.m8n8.x4.shared.b16 {%0,%1,%2,%3}, [%4];"
                 : "=r"(r[0]), "=r"(r[1]), "=r"(r[2]), "=r"(r[3]) : "r"(addr));
}

__device__ __forceinline__ uint32_t smem_u32(const void* p) {
    uint32_t a;
    asm("{ .reg .u64 t; cvta.to.shared.u64 t, %1; cvt.u32.u64 %0, t; }" : "=r"(a) : "l"(p));
    return a;
}

// split f32 pair -> packed bf16x2 (hi, lo)
__device__ __forceinline__ void split2(float x, float y, uint32_t& hi, uint32_t& lo) {
    __nv_bfloat16 hx = __float2bfloat16(x), hy = __float2bfloat16(y);
    __nv_bfloat162 h; h.x = hx; h.y = hy;
    __nv_bfloat162 l; l.x = __float2bfloat16(x - __bfloat162float(hx));
                      l.y = __float2bfloat16(y - __bfloat162float(hy));
    hi = *(uint32_t*)&h;
    lo = *(uint32_t*)&l;
}

// ---------------- degree + count ----------------
__global__ void k_deg_init() {
    int i = blockIdx.x * blockDim.x + threadIdx.x;
    if (i < NN) g_dc[i] = make_float2(1.0f, 0.0f);   // self-loop weight 1
}

__global__ void k_deg_acc(const int* __restrict__ ei, const float* __restrict__ w) {
    int e = blockIdx.x * blockDim.x + threadIdx.x;
    if (e < EE) {
        int c = ei[EE + e];
        asm volatile("red.global.add.v2.f32 [%0], {%1, %2};"
                     :: "l"(&g_dc[c]), "f"(w[e]), "f"(1.0f) : "memory");
    }
}

// ---------------- exclusive scan over cnt -> g_rowptr ----------------
__global__ void k_scan1() {
    __shared__ int sh[SCAN_BLK];
    int i = blockIdx.x * SCAN_BLK + threadIdx.x;
    int v = (i < NN) ? (int)g_dc[i].y : 0;
    sh[threadIdx.x] = v;
    __syncthreads();
    for (int off = 1; off < SCAN_BLK; off <<= 1) {
        int t = (threadIdx.x >= off) ? sh[threadIdx.x - off] : 0;
        __syncthreads();
        sh[threadIdx.x] += t;
        __syncthreads();
    }
    if (i < NN) g_rowptr[i] = sh[threadIdx.x] - v;
    if (threadIdx.x == SCAN_BLK - 1) g_bsum[blockIdx.x] = sh[threadIdx.x];
}

// scan_add with inline top-level prefix; also computes dinv
__global__ void k_scan_add() {
    __shared__ int sred[128];
    int tidx = threadIdx.x;
    if (tidx < 128)
        sred[tidx] = (tidx < NBLK && tidx < blockIdx.x) ? g_bsum[tidx] : 0;
    __syncthreads();
    if (tidx < 64) sred[tidx] += sred[tidx + 64];
    __syncthreads();
    if (tidx < 32) {
        int s = sred[tidx] + sred[tidx + 32];
        s += __shfl_down_sync(0xffffffffu, s, 16);
        s += __shfl_down_sync(0xffffffffu, s, 8);
        s += __shfl_down_sync(0xffffffffu, s, 4);
        s += __shfl_down_sync(0xffffffffu, s, 2);
        s += __shfl_down_sync(0xffffffffu, s, 1);
        if (tidx == 0) sred[0] = s;
    }
    __syncthreads();
    int prefix = sred[0];

    int i = blockIdx.x * SCAN_BLK + tidx;
    if (i < NN) {
        int r = g_rowptr[i] + prefix;
        g_rowptr[i] = r;
        g_cursor[i] = r;
        float d = g_dc[i].x;
        g_deg[i] = d > 0.f ? rsqrtf(fmaxf(d, 1e-30f)) : 0.f;
    }
    if (i == 0) g_rowptr[NN] = EE;
}

// ---------------- CSR fill (packed int2) ----------------
__global__ void k_fill(const int* __restrict__ ei, const float* __restrict__ w) {
    int e = blockIdx.x * blockDim.x + threadIdx.x;
    if (e < EE) {
        int r = ei[e];
        int c = ei[EE + e];
        int pos = atomicAdd(&g_cursor[c], 1);
        float nm = g_deg[r] * w[e] * g_deg[c];
        g_ce[pos] = make_int2(r, __float_as_int(nm));
    }
}

// ---------------- conv weights -> split-bf16 images, [n][k] -----------------
__global__ void k_wb(const float* __restrict__ W0, const float* __restrict__ W1) {
    int i = blockIdx.x * blockDim.x + threadIdx.x;
    if (i < 512 * 64) {
        int k = i >> 6, n = i & 63;
        float w = W0[i];
        __nv_bfloat16 hi = __float2bfloat16(w);
        __nv_bfloat16 lo = __float2bfloat16(w - __bfloat162float(hi));
        g_wbh[n * 512 + k] = hi;
        g_wbl[n * 512 + k] = lo;
    } else if (i < 512 * 64 + 64 * 64) {
        int r = i - 512 * 64;
        int k = r >> 6, n = r & 63;
        float w = W1[r];
        __nv_bfloat16 hi = __float2bfloat16(w);
        __nv_bfloat16 lo = __float2bfloat16(w - __bfloat162float(hi));
        g_w1h[n * 64 + k] = hi;
        g_w1l[n * 64 + k] = lo;
    }
}

// ---------------- dense weights -> split-bf16 images ------------------------
__global__ void k_wd(const float* __restrict__ w0, const float* __restrict__ w1,
                     const float* __restrict__ w2, const float* __restrict__ w3) {
    int i = blockIdx.x * blockDim.x + threadIdx.x;
    if (i < 3 * 4096) {
        int L = i >> 12, r = i & 4095;
        int k = r >> 6, n = r & 63;
        const float* W = (L == 0) ? w0 : ((L == 1) ? w1 : w2);
        float v = W[k * 64 + n];
        __nv_bfloat16 hi = __float2bfloat16(v);
        __nv_bfloat16 lo = __float2bfloat16(v - __bfloat162float(hi));
        g_wdh[L * 4096 + n * 64 + k] = hi;
        g_wdl[L * 4096 + n * 64 + k] = lo;
    } else if (i < 3 * 4096 + 2048) {
        int r = i - 12288;
        int n = r >> 6, k = r & 63;
        float v = (n < 20) ? w3[k * 20 + n] : 0.f;
        __nv_bfloat16 hi = __float2bfloat16(v);
        __nv_bfloat16 lo = __float2bfloat16(v - __bfloat162float(hi));
        g_w3h[n * 64 + k] = hi;
        g_w3l[n * 64 + k] = lo;
    }
}

// ---------------- generic conv GEMM on mma.sync (split-bf16, ldmatrix) -----
#define ASTR 72
#define SM_AHI_O 0
#define SM_ALO_O 18432
#define SM_BHI_O 36864
#define SM_BLO_O 46080
#define SM_MMA_TOT 55296
__global__ void k_conv_mma(const float* __restrict__ A, float* __restrict__ C, int M, int K,
                           const __nv_bfloat16* __restrict__ WH,
                           const __nv_bfloat16* __restrict__ WL) {
    extern __shared__ __align__(16) char smem[];
    __nv_bfloat16* Ah = (__nv_bfloat16*)(smem + SM_AHI_O);
    __nv_bfloat16* Al = (__nv_bfloat16*)(smem + SM_ALO_O);
    __nv_bfloat16* Bh = (__nv_bfloat16*)(smem + SM_BHI_O);
    __nv_bfloat16* Bl = (__nv_bfloat16*)(smem + SM_BLO_O);

    int tid = threadIdx.x;
    int w = tid >> 5, lane = tid & 31;
    int gr = lane >> 2, t = lane & 3;
    int row0 = blockIdx.x * 128;
    uint32_t sb = smem_u32(smem);

    uint32_t a_off = (uint32_t)((w * 16 + (lane & 7) + ((lane >> 3) & 1) * 8) * 144
                                + ((lane >> 4) & 1) * 16);
    uint32_t b_off_base = (uint32_t)((((lane >> 4) & 1) * 8 + (lane & 7)) * 144
                                     + ((lane >> 3) & 1) * 16);

    float acc[8][4];
#pragma unroll
    for (int i = 0; i < 8; i++)
#pragma unroll
        for (int j = 0; j < 4; j++) acc[i][j] = 0.f;

    int chunks = K >> 6;
    for (int c = 0; c < chunks; c++) {
#pragma unroll
        for (int it = 0; it < 8; it++) {
            int idx = tid + it * 256;
            int r = idx >> 4;
            int kq = (idx & 15) * 4;
            int row = row0 + r;
            float4 v = (row < M) ? *(const float4*)&A[(size_t)row * K + c * 64 + kq]
                                 : make_float4(0.f, 0.f, 0.f, 0.f);
            uint32_t h0, l0, h1, l1;
            split2(v.x, v.y, h0, l0);
            split2(v.z, v.w, h1, l1);
            int so = r * ASTR + kq;
            *(uint32_t*)(Ah + so)     = h0;
            *(uint32_t*)(Ah + so + 2) = h1;
            *(uint32_t*)(Al + so)     = l0;
            *(uint32_t*)(Al + so + 2) = l1;
        }
#pragma unroll
        for (int it = 0; it < 2; it++) {
            int i = tid + it * 256;
            int n = i >> 3, j = i & 7;
            uint4 vh = *((const uint4*)(WH + (size_t)n * K + c * 64) + j);
            uint4 vl = *((const uint4*)(WL + (size_t)n * K + c * 64) + j);
            *((uint4*)((char*)Bh + n * 144) + j) = vh;
            *((uint4*)((char*)Bl + n * 144) + j) = vl;
        }
        __syncthreads();

#pragma unroll
        for (int ks = 0; ks < 4; ks++) {
            uint32_t kadd = (uint32_t)(ks * 32);
            uint32_t ah[4], al[4];
            ldsm4(ah, sb + SM_AHI_O + a_off + kadd);
            ldsm4(al, sb + SM_ALO_O + a_off + kadd);
#pragma unroll
            for (int p = 0; p < 4; p++) {
                uint32_t boff = b_off_base + (uint32_t)(p * 16 * 144) + kadd;
                uint32_t bh[4], bl[4];
                ldsm4(bh, sb + SM_BHI_O + boff);
                ldsm4(bl, sb + SM_BLO_O + boff);
                mma_bf16(acc[2 * p],     ah, bh[0], bh[1]);
                mma_bf16(acc[2 * p],     al, bh[0], bh[1]);
                mma_bf16(acc[2 * p],     ah, bl[0], bl[1]);
                mma_bf16(acc[2 * p + 1], ah, bh[2], bh[3]);
                mma_bf16(acc[2 * p + 1], al, bh[2], bh[3]);
                mma_bf16(acc[2 * p + 1], ah, bl[2], bl[3]);
            }
        }
        __syncthreads();
    }

    int r1 = row0 + w * 16 + gr;
    int r2 = r1 + 8;
#pragma unroll
    for (int nt = 0; nt < 8; nt++) {
        int col = nt * 8 + t * 2;
        if (r1 < M) *(float2*)&C[(size_t)r1 * 64 + col] = make_float2(acc[nt][0], acc[nt][1]);
        if (r2 < M) *(float2*)&C[(size_t)r2 * 64 + col] = make_float2(acc[nt][2], acc[nt][3]);
    }
}

// ---------------- CSR gather + self-loop + bias + SELU -> g_h --------------
// standalone (max occupancy), edge loop unrolled x4 for MLP
__global__ void __launch_bounds__(256, 8)
k_gather(const float* __restrict__ bias) {
    int t = blockIdx.x * blockDim.x + threadIdx.x;
    if (t >= NN * 16) return;
    int n = t >> 4;
    int q = (t & 15) << 2;

    float d = g_deg[n];
    float dd = d * d;
    float4 v = *(const float4*)&g_xw[(size_t)n * 64 + q];
    float4 acc = make_float4(v.x * dd, v.y * dd, v.z * dd, v.w * dd);

    int s = g_rowptr[n], e2 = g_rowptr[n + 1];
    int i = s;
    for (; i + 3 < e2; i += 4) {
        int2 p0 = g_ce[i];
        int2 p1 = g_ce[i + 1];
        int2 p2 = g_ce[i + 2];
        int2 p3 = g_ce[i + 3];
        float4 u0 = *(const float4*)&g_xw[(size_t)p0.x * 64 + q];
        float4 u1 = *(const float4*)&g_xw[(size_t)p1.x * 64 + q];
        float4 u2 = *(const float4*)&g_xw[(size_t)p2.x * 64 + q];
        float4 u3 = *(const float4*)&g_xw[(size_t)p3.x * 64 + q];
        float n0 = __int_as_float(p0.y), n1 = __int_as_float(p1.y);
        float n2 = __int_as_float(p2.y), n3 = __int_as_float(p3.y);
        acc.x += n0 * u0.x + n1 * u1.x + n2 * u2.x + n3 * u3.x;
        acc.y += n0 * u0.y + n1 * u1.y + n2 * u2.y + n3 * u3.y;
        acc.z += n0 * u0.z + n1 * u1.z + n2 * u2.z + n3 * u3.z;
        acc.w += n0 * u0.w + n1 * u1.w + n2 * u2.w + n3 * u3.w;
    }
    for (; i < e2; i++) {
        int2 p0 = g_ce[i];
        float n0 = __int_as_float(p0.y);
        float4 u0 = *(const float4*)&g_xw[(size_t)p0.x * 64 + q];
        acc.x += n0 * u0.x;
        acc.y += n0 * u0.y;
        acc.z += n0 * u0.z;
        acc.w += n0 * u0.w;
    }

    float4 b4 = *(const float4*)&bias[q];
    float4 o;
    o.x = selu_f(acc.x + b4.x);
    o.y = selu_f(acc.y + b4.y);
    o.z = selu_f(acc.z + b4.z);
    o.w = selu_f(acc.w + b4.w);
    *(float4*)&g_h[(size_t)n * 64 + q] = o;
}

// ---------------- dense MLP on mma.sync: 3x(64x64)+SELU, 64x20, softmax ----
#define DM_AH 0
#define DM_AL 18432
#define DM_BH 36864
#define DM_BL 46080
#define DM_BS 55296
#define DM_TOT 55552
__global__ void k_dense_mma(const float* __restrict__ b0, const float* __restrict__ b1,
                            const float* __restrict__ b2, const float* __restrict__ b3,
                            float* __restrict__ out, int M) {
    extern __shared__ __align__(16) char smem[];
    __nv_bfloat16* Ah = (__nv_bfloat16*)(smem + DM_AH);
    __nv_bfloat16* Al = (__nv_bfloat16*)(smem + DM_AL);
    float* bs = (float*)(smem + DM_BS);

    int tid = threadIdx.x;
    int w = tid >> 5, lane = tid & 31;
    int gr = lane >> 2, t = lane & 3;
    int row0 = blockIdx.x * 128;
    uint32_t sb = smem_u32(smem);

    uint32_t a_off = (uint32_t)((w * 16 + (lane & 7) + ((lane >> 3) & 1) * 8) * 144
                                + ((lane >> 4) & 1) * 16);
    uint32_t b_off_base = (uint32_t)((((lane >> 4) & 1) * 8 + (lane & 7)) * 144
                                     + ((lane >> 3) & 1) * 16);

    // initial A: g_h -> split bf16 smem
#pragma unroll
    for (int it = 0; it < 8; it++) {
        int idx = tid + it * 256;
        int r = idx >> 4;
        int kq = (idx & 15) * 4;
        int row = row0 + r;
        float4 v = (row < M) ? *(const float4*)&g_h[(size_t)row * 64 + kq]
                             : make_float4(0.f, 0.f, 0.f, 0.f);
        uint32_t h0, l0, h1, l1;
        split2(v.x, v.y, h0, l0);
        split2(v.z, v.w, h1, l1);
        int so = r * ASTR + kq;
        *(uint32_t*)(Ah + so)     = h0;
        *(uint32_t*)(Ah + so + 2) = h1;
        *(uint32_t*)(Al + so)     = l0;
        *(uint32_t*)(Al + so + 2) = l1;
    }

    const float* Bp[3] = {b0, b1, b2};

    for (int L = 0; L < 3; L++) {
#pragma unroll
        for (int it = 0; it < 2; it++) {
            int i = tid + it * 256;
            int n = i >> 3, j = i & 7;
            uint4 vh = *((const uint4*)(g_wdh + L * 4096 + n * 64) + j);
            uint4 vl = *((const uint4*)(g_wdl + L * 4096 + n * 64) + j);
            *((uint4*)(smem + DM_BH + n * 144) + j) = vh;
            *((uint4*)(smem + DM_BL + n * 144) + j) = vl;
        }
        if (tid < 64) bs[tid] = Bp[L][tid];
        __syncthreads();

        float acc[8][4];
#pragma unroll
        for (int i = 0; i < 8; i++)
#pragma unroll
            for (int j = 0; j < 4; j++) acc[i][j] = 0.f;

#pragma unroll
        for (int ks = 0; ks < 4; ks++) {
            uint32_t kadd = (uint32_t)(ks * 32);
            uint32_t ah[4], al[4];
            ldsm4(ah, sb + DM_AH + a_off + kadd);
            ldsm4(al, sb + DM_AL + a_off + kadd);
#pragma unroll
            for (int p = 0; p < 4; p++) {
                uint32_t boff = b_off_base + (uint32_t)(p * 16 * 144) + kadd;
                uint32_t bh[4], bl[4];
                ldsm4(bh, sb + DM_BH + boff);
                ldsm4(bl, sb + DM_BL + boff);
                mma_bf16(acc[2 * p],     ah, bh[0], bh[1]);
                mma_bf16(acc[2 * p],     al, bh[0], bh[1]);
                mma_bf16(acc[2 * p],     ah, bl[0], bl[1]);
                mma_bf16(acc[2 * p + 1], ah, bh[2], bh[3]);
                mma_bf16(acc[2 * p + 1], al, bh[2], bh[3]);
                mma_bf16(acc[2 * p + 1], ah, bl[2], bl[3]);
            }
        }

        uint32_t whi[8][2], wlo[8][2];
#pragma unroll
        for (int nt = 0; nt < 8; nt++) {
            float2 bb = *(const float2*)&bs[nt * 8 + 2 * t];
            float c0 = selu_f(acc[nt][0] + bb.x);
            float c1 = selu_f(acc[nt][1] + bb.y);
            float c2 = selu_f(acc[nt][2] + bb.x);
            float c3 = selu_f(acc[nt][3] + bb.y);
            split2(c0, c1, whi[nt][0], wlo[nt][0]);
            split2(c2, c3, whi[nt][1], wlo[nt][1]);
        }
        __syncthreads();
        int ra = (w * 16 + gr) * ASTR;
        int rb = (w * 16 + gr + 8) * ASTR;
#pragma unroll
        for (int nt = 0; nt < 8; nt++) {
            int co = nt * 8 + 2 * t;
            *(uint32_t*)(Ah + ra + co) = whi[nt][0];
            *(uint32_t*)(Al + ra + co) = wlo[nt][0];
            *(uint32_t*)(Ah + rb + co) = whi[nt][1];
            *(uint32_t*)(Al + rb + co) = wlo[nt][1];
        }
        __syncthreads();
    }

    // final layer: W3 padded to 32 rows
    {
        int i = tid;
        int n = i >> 3, j = i & 7;
        uint4 vh = *((const uint4*)(g_w3h + n * 64) + j);
        uint4 vl = *((const uint4*)(g_w3l + n * 64) + j);
        *((uint4*)(smem + DM_BH + n * 144) + j) = vh;
        *((uint4*)(smem + DM_BL + n * 144) + j) = vl;
    }
    if (tid < 24) bs[tid] = (tid < 20) ? b3[tid] : 0.f;
    __syncthreads();

    float accf[4][4];
#pragma unroll
    for (int i = 0; i < 4; i++)
#pragma unroll
        for (int j = 0; j < 4; j++) accf[i][j] = 0.f;

#pragma unroll
    for (int ks = 0; ks < 4; ks++) {
        uint32_t kadd = (uint32_t)(ks * 32);
        uint32_t ah[4], al[4];
        ldsm4(ah, sb + DM_AH + a_off + kadd);
        ldsm4(al, sb + DM_AL + a_off + kadd);
#pragma unroll
        for (int p = 0; p < 2; p++) {
            uint32_t boff = b_off_base + (uint32_t)(p * 16 * 144) + kadd;
            uint32_t bh[4], bl[4];
            ldsm4(bh, sb + DM_BH + boff);
            ldsm4(bl, sb + DM_BL + boff);
            mma_bf16(accf[2 * p],     ah, bh[0], bh[1]);
            mma_bf16(accf[2 * p],     al, bh[0], bh[1]);
            mma_bf16(accf[2 * p],     ah, bl[0], bl[1]);
            mma_bf16(accf[2 * p + 1], ah, bh[2], bh[3]);
            mma_bf16(accf[2 * p + 1], al, bh[2], bh[3]);
            mma_bf16(accf[2 * p + 1], ah, bl[2], bl[3]);
        }
    }

    float lg0[6], lg1[6];
#pragma unroll
    for (int nt = 0; nt < 3; nt++) {
        float2 bb = *(const float2*)&bs[nt * 8 + 2 * t];
        lg0[2 * nt]     = accf[nt][0] + bb.x;
        lg0[2 * nt + 1] = accf[nt][1] + bb.y;
        lg1[2 * nt]     = accf[nt][2] + bb.x;
        lg1[2 * nt + 1] = accf[nt][3] + bb.y;
    }
    bool v4 = (16 + 2 * t) < 20;
    if (!v4) { lg0[4] = lg0[5] = lg1[4] = lg1[5] = -1e30f; }

    float m0 = lg0[0], m1 = lg1[0];
#pragma unroll
    for (int i = 1; i < 6; i++) { m0 = fmaxf(m0, lg0[i]); m1 = fmaxf(m1, lg1[i]); }
    m0 = fmaxf(m0, __shfl_xor_sync(0xffffffffu, m0, 1));
    m0 = fmaxf(m0, __shfl_xor_sync(0xffffffffu, m0, 2));
    m1 = fmaxf(m1, __shfl_xor_sync(0xffffffffu, m1, 1));
    m1 = fmaxf(m1, __shfl_xor_sync(0xffffffffu, m1, 2));

    float e0[6], e1[6], s0 = 0.f, s1 = 0.f;
#pragma unroll
    for (int i = 0; i < 6; i++) {
        e0[i] = expf(lg0[i] - m0);
        e1[i] = expf(lg1[i] - m1);
        s0 += e0[i];
        s1 += e1[i];
    }
    s0 += __shfl_xor_sync(0xffffffffu, s0, 1);
    s0 += __shfl_xor_sync(0xffffffffu, s0, 2);
    s1 += __shfl_xor_sync(0xffffffffu, s1, 1);
    s1 += __shfl_xor_sync(0xffffffffu, s1, 2);
    float i0 = 1.f / s0, i1 = 1.f / s1;

    int r1 = row0 + w * 16 + gr;
    int r2 = r1 + 8;
#pragma unroll
    for (int nt = 0; nt < 3; nt++) {
        if (nt == 2 && !v4) continue;
        int col = nt * 8 + 2 * t;
        if (r1 < M) *(float2*)&out[(size_t)r1 * 20 + col] = make_float2(e0[2 * nt] * i0, e0[2 * nt + 1] * i0);
        if (r2 < M) *(float2*)&out[(size_t)r2 * 20 + col] = make_float2(e1[2 * nt] * i1, e1[2 * nt + 1] * i1);
    }
}

// ---------------- launch ----------------
extern "C" void kernel_launch(void* const* d_in, const int* in_sizes, int n_in,
                              void* d_out, int out_size) {
    const float* x    = (const float*)d_in[0];
    const int*   ei   = (const int*)d_in[1];      // int32 (JAX x64 disabled)
    const float* ea   = (const float*)d_in[2];
    const float* gc0w = (const float*)d_in[3];
    const float* gc0b = (const float*)d_in[4];
    const float* gc1w = (const float*)d_in[5];
    const float* gc1b = (const float*)d_in[6];
    const float* l0w  = (const float*)d_in[7];
    const float* l0b  = (const float*)d_in[8];
    const float* l1w  = (const float*)d_in[9];
    const float* l1b  = (const float*)d_in[10];
    const float* l2w  = (const float*)d_in[11];
    const float* l2b  = (const float*)d_in[12];
    const float* l3w  = (const float*)d_in[13];
    const float* l3b  = (const float*)d_in[14];
    float*       out  = (float*)d_out;

    float *xw, *h;
    cudaGetSymbolAddress((void**)&xw, g_xw);
    cudaGetSymbolAddress((void**)&h,  g_h);
    __nv_bfloat16 *wbh, *wbl, *w1h, *w1l;
    cudaGetSymbolAddress((void**)&wbh, g_wbh);
    cudaGetSymbolAddress((void**)&wbl, g_wbl);
    cudaGetSymbolAddress((void**)&w1h, g_w1h);
    cudaGetSymbolAddress((void**)&w1l, g_w1l);

    cudaFuncSetAttribute(k_conv_mma, cudaFuncAttributeMaxDynamicSharedMemorySize, SM_MMA_TOT);
    cudaFuncSetAttribute(k_dense_mma, cudaFuncAttributeMaxDynamicSharedMemorySize, DM_TOT);

    // second stream + fork/join events (host-side objects, created once)
    static cudaStream_t s2 = nullptr;
    static cudaEvent_t ev_fork = nullptr, ev_join = nullptr;
    if (s2 == nullptr) {
        cudaStreamCreateWithFlags(&s2, cudaStreamNonBlocking);
        cudaEventCreateWithFlags(&ev_fork, cudaEventDisableTiming);
        cudaEventCreateWithFlags(&ev_join, cudaEventDisableTiming);
    }

    const int T = 256;

    // fork: branch B (weight images + conv0 GEMM) on s2
    cudaEventRecord(ev_fork, 0);
    cudaStreamWaitEvent(s2, ev_fork, 0);
    k_wb<<<(512 * 64 + 64 * 64 + T - 1) / T, T, 0, s2>>>(gc0w, gc1w);
    k_wd<<<(14336 + T - 1) / T, T, 0, s2>>>(l0w, l1w, l2w, l3w);
    k_conv_mma<<<(NN + 127) / 128, T, SM_MMA_TOT, s2>>>(x, xw, NN, IND, wbh, wbl);
    cudaEventRecord(ev_join, s2);

    // branch A (CSR build) on default stream
    k_deg_init<<<(NN + T - 1) / T, T>>>();
    k_deg_acc<<<(EE + T - 1) / T, T>>>(ei, ea);
    k_scan1<<<NBLK, SCAN_BLK>>>();
    k_scan_add<<<NBLK, SCAN_BLK>>>();
    k_fill<<<(EE + T - 1) / T, T>>>(ei, ea);

    // join: gather0 needs CSR (branch A) + xw (branch B)
    cudaStreamWaitEvent(0, ev_join, 0);
    k_gather<<<(NN * 16 + T - 1) / T, T>>>(gc0b);

    // conv 1 (K=64) + gather 1
    k_conv_mma<<<(NN + 127) / 128, T, SM_MMA_TOT>>>(h, xw, NN, HGD, w1h, w1l);
    k_gather<<<(NN * 16 + T - 1) / T, T>>>(gc1b);

    // dense stack + softmax on tensor cores
    k_dense_mma<<<(NN + 127) / 128, T, DM_TOT>>>(l0b, l1b, l2b, l3b, out, NN);
}